// round 13
// baseline (speedup 1.0000x reference)
#include <cuda_runtime.h>
#include <cuda_bf16.h>
#include <cuda_fp8.h>
#include <math.h>
#include <cstdint>

#define BB 2
#define LL 1024
#define DM 768
#define DI 1536
#define DS 16
#define DD 48
#define NTOK (BB*LL)
#define XPE 80   // D_DELTA + 2*D_STATE

#define NSEG 16
#define SEGL 64
#define NGB  (BB*DI/16)      // 192
#define LANES (BB*DI*DS)     // 49152

typedef __nv_bfloat16 bf16;
typedef uint8_t fp8;

#define WSCALE     64.0f
#define WSCALE_INV 0.015625f

// ---------------- scratch ----------------
__device__ fp8   g8_xn[NTOK*DM];
__device__ bf16  gb_xz[NTOK*2*DI];
__device__ bf16  gb_xc[NTOK*DI];
__device__ float g_dbc[NTOK*XPE];
__device__ fp8   g8_y[NTOK*DI];
__device__ float g_sumA[NSEG*LANES];
__device__ float g_sumB[NSEG*LANES];
__device__ int   g_flags[NSEG*LANES];
__device__ fp8   g8_inw[2*2*DI*DM];
__device__ fp8   g8_ow [2*DM*DI];
__device__ bf16  gb_xpw[2*XPE*DI];

__device__ __forceinline__ float sigmoidf_(float x){ return 1.f/(1.f+__expf(-x)); }
__device__ __forceinline__ float softplus_(float v){ return v > 20.f ? v : log1pf(expf(v)); }
__device__ __forceinline__ fp8 f2e4(float x){
    return (fp8)__nv_cvt_float_to_fp8(x, __NV_SATFINITE, __NV_E4M3);
}
__device__ __forceinline__ uint32_t pkbf(float a, float b){
    __nv_bfloat162 t = __floats2bfloat162_rn(a, b);
    return *(uint32_t*)&t;
}
__device__ __forceinline__ uint32_t smem_u32(const void* p){
    uint32_t a; asm("{ .reg .u64 t; cvta.to.shared.u64 t, %1; cvt.u32.u64 %0, t; }" : "=r"(a) : "l"(p));
    return a;
}

// ---------------- weight converts (2 kernels) ----------------
__global__ void wq2_kernel(const float* __restrict__ a, fp8* __restrict__ ao, int na,
                           const float* __restrict__ b, fp8* __restrict__ bo, int nb)
{
    int i = (blockIdx.x*256 + threadIdx.x)*4;
    const float* src; fp8* dst; int off;
    if (i < na)            { src = a; dst = ao; off = i; }
    else if (i < na + nb)  { src = b; dst = bo; off = i - na; }
    else return;
    float4 v = *(const float4*)(src + off);
    *(uint32_t*)(dst + off) = (uint32_t)f2e4(v.x*WSCALE)
        | ((uint32_t)f2e4(v.y*WSCALE)<<8) | ((uint32_t)f2e4(v.z*WSCALE)<<16)
        | ((uint32_t)f2e4(v.w*WSCALE)<<24);
}
__global__ void f2bf_kernel(const float* __restrict__ a, bf16* __restrict__ ao, int n)
{
    int i = (blockIdx.x*256 + threadIdx.x)*4;
    if (i >= n) return;
    float4 v = *(const float4*)(a + i);
    *(uint32_t*)(ao + i)   = pkbf(v.x, v.y);
    *(uint32_t*)(ao + i+2) = pkbf(v.z, v.w);
}

// ---------------- rmsnorm ----------------
__global__ void rmsnorm_kernel(const float* __restrict__ x, const float* __restrict__ w,
                               fp8* __restrict__ out)
{
    int tok = blockIdx.x;
    int tid = threadIdx.x;
    const float* xr = x + (size_t)tok*DM;
    float v0 = xr[tid], v1 = xr[tid+256], v2 = xr[tid+512];
    float s = v0*v0 + v1*v1 + v2*v2;
    #pragma unroll
    for (int o=16;o>0;o>>=1) s += __shfl_xor_sync(0xffffffffu, s, o);
    __shared__ float red[8];
    if ((tid&31)==0) red[tid>>5] = s;
    __syncthreads();
    float tot = red[0]+red[1]+red[2]+red[3]+red[4]+red[5]+red[6]+red[7];
    float r = rsqrtf(tot * (1.f/768.f) + 1e-5f);
    fp8* o = out + (size_t)tok*DM;
    o[tid]     = f2e4(w[tid]     * v0 * r);
    o[tid+256] = f2e4(w[tid+256] * v1 * r);
    o[tid+512] = f2e4(w[tid+512] * v2 * r);
}

// =====================================================================
// cp.async + ldmatrix tensor GEMM (R10/R12-proven, unchanged).
// =====================================================================
template<int EPI, int ESZ, bool NGUARD>
__global__ void __launch_bounds__(256, 2)
gemm_cp(const uint8_t* __restrict__ A, const uint8_t* __restrict__ B,
        void* __restrict__ Cv, int M, int N, int KlenB,
        int ldaB, int ldbB, int ldc)
{
    extern __shared__ uint8_t smem[];
    uint32_t sbase = smem_u32(smem);

    int tid = threadIdx.x;
    int lane = tid & 31;
    int w    = tid >> 5;
    int wm   = w & 1;
    int wn   = w >> 1;
    int m0 = blockIdx.y * 128;
    int n0 = blockIdx.x * 128;
    int kbegB = blockIdx.z * KlenB;

    const uint8_t* Agb = A + (size_t)m0*ldaB + kbegB;
    const uint8_t* Bgb = B + (size_t)n0*ldbB + kbegB;

    auto a_off = [](int r, int cx)->uint32_t {
        uint32_t c8 = (uint32_t)((((r&1)<<2) + cx) ^ ((r>>1)&7));
        return (uint32_t)((r>>1)*128) + c8*16;
    };

    const int KT = KlenB / 64;

    auto issue = [&](int kt){
        if (kt < KT){
            uint32_t st = sbase + (uint32_t)(kt%3)*16384u;
            #pragma unroll
            for (int i=0;i<2;i++){
                int q = tid + i*256;
                int r = q >> 2, cx = q & 3;
                const uint8_t* ga = Agb + (size_t)r*ldaB + kt*64 + cx*16;
                uint32_t da = st + a_off(r, cx);
                asm volatile("cp.async.cg.shared.global [%0], [%1], 16;" :: "r"(da), "l"(ga));
                int rb = (NGUARD && (n0 + r >= N)) ? 0 : r;
                const uint8_t* gb = Bgb + (size_t)rb*ldbB + kt*64 + cx*16;
                uint32_t db = st + 8192u + a_off(r, cx);
                if (NGUARD){
                    unsigned ssz = (n0 + r < N) ? 16u : 0u;
                    asm volatile("cp.async.cg.shared.global [%0], [%1], 16, %2;" :: "r"(db), "l"(gb), "r"(ssz));
                } else {
                    asm volatile("cp.async.cg.shared.global [%0], [%1], 16;" :: "r"(db), "l"(gb));
                }
            }
        }
        asm volatile("cp.async.commit_group;");
    };

    float acc[4][4][4];
    #pragma unroll
    for (int i=0;i<4;i++)
        #pragma unroll
        for (int j=0;j<4;j++)
            #pragma unroll
            for (int e=0;e<4;e++) acc[i][j][e]=0.f;

    issue(0);
    issue(1);

    int mi   = lane >> 3;
    int lrow = lane & 7;

    for (int kt=0; kt<KT; kt++){
        asm volatile("cp.async.wait_group 1;" ::: "memory");
        __syncthreads();
        issue(kt+2);

        uint32_t st = sbase + (uint32_t)(kt%3)*16384u;
        #pragma unroll
        for (int g2=0; g2<2; g2++){
            uint32_t av[4][4];
            #pragma unroll
            for (int i=0;i<4;i++){
                int row = wm*64 + i*16 + ((mi&1)<<3) + lrow;
                int cx  = 2*g2 + (mi>>1);
                uint32_t ad = st + a_off(row, cx);
                asm volatile("ldmatrix.sync.aligned.m8n8.x4.shared.b16 {%0,%1,%2,%3}, [%4];"
                    : "=r"(av[i][0]), "=r"(av[i][1]), "=r"(av[i][2]), "=r"(av[i][3])
                    : "r"(ad));
            }
            uint32_t bv[4][2];
            #pragma unroll
            for (int P=0; P<2; P++){
                int nrow = wn*32 + (2*P + (mi>>1))*8 + lrow;
                int cx   = 2*g2 + (mi&1);
                uint32_t bd = st + 8192u + a_off(nrow, cx);
                asm volatile("ldmatrix.sync.aligned.m8n8.x4.shared.b16 {%0,%1,%2,%3}, [%4];"
                    : "=r"(bv[2*P][0]), "=r"(bv[2*P][1]), "=r"(bv[2*P+1][0]), "=r"(bv[2*P+1][1])
                    : "r"(bd));
            }
            #pragma unroll
            for (int i=0;i<4;i++)
                #pragma unroll
                for (int j=0;j<4;j++){
                    if (ESZ == 1){
                        asm volatile(
                            "mma.sync.aligned.m16n8k32.row.col.f32.e4m3.e4m3.f32 "
                            "{%0,%1,%2,%3}, {%4,%5,%6,%7}, {%8,%9}, {%0,%1,%2,%3};"
                            : "+f"(acc[i][j][0]), "+f"(acc[i][j][1]),
                              "+f"(acc[i][j][2]), "+f"(acc[i][j][3])
                            : "r"(av[i][0]), "r"(av[i][1]), "r"(av[i][2]), "r"(av[i][3]),
                              "r"(bv[j][0]), "r"(bv[j][1]));
                    } else {
                        asm volatile(
                            "mma.sync.aligned.m16n8k16.row.col.f32.bf16.bf16.f32 "
                            "{%0,%1,%2,%3}, {%4,%5,%6,%7}, {%8,%9}, {%0,%1,%2,%3};"
                            : "+f"(acc[i][j][0]), "+f"(acc[i][j][1]),
                              "+f"(acc[i][j][2]), "+f"(acc[i][j][3])
                            : "r"(av[i][0]), "r"(av[i][1]), "r"(av[i][2]), "r"(av[i][3]),
                              "r"(bv[j][0]), "r"(bv[j][1]));
                    }
                }
        }
        __syncthreads();
    }

    const float SCL = (ESZ == 1) ? WSCALE_INV : 1.0f;
    float* C  = (float*)Cv;
    bf16*  Cb = (bf16*)Cv;
    int g4c = lane >> 2, tc = lane & 3;
    #pragma unroll
    for (int i=0;i<4;i++){
        int row = m0 + (wm*4 + i)*16 + g4c;
        #pragma unroll
        for (int j=0;j<4;j++){
            int col = n0 + (wn*4 + j)*8 + tc*2;
            if (NGUARD && col >= N) continue;
            float v0 = acc[i][j][0]*SCL, v1 = acc[i][j][1]*SCL;
            float v2 = acc[i][j][2]*SCL, v3 = acc[i][j][3]*SCL;
            if (EPI == 1){
                float* cp0 = C + (size_t)row*ldc + col;
                float* cp1 = C + (size_t)(row+8)*ldc + col;
                atomicAdd(cp0,   v0);
                atomicAdd(cp0+1, v1);
                atomicAdd(cp1,   v2);
                atomicAdd(cp1+1, v3);
            } else {
                *(__nv_bfloat162*)(Cb + (size_t)row*ldc + col)     = __floats2bfloat162_rn(v0, v1);
                *(__nv_bfloat162*)(Cb + (size_t)(row+8)*ldc + col) = __floats2bfloat162_rn(v2, v3);
            }
        }
    }
}

// ---------------- conv + SiLU; also zeroes dbc and scan flags ----------------
__global__ void conv_silu_kernel(const bf16* __restrict__ xz, const float* __restrict__ cw,
                                 const float* __restrict__ cb, bf16* __restrict__ xc,
                                 float* __restrict__ dbc, int* __restrict__ flags)
{
    int idx = blockIdx.x*blockDim.x + threadIdx.x;
    if (idx < NTOK*XPE) dbc[idx] = 0.f;
    if (idx < NSEG*LANES) flags[idx] = 0;
    int d = idx % DI;
    int tok = idx / DI;
    int l = tok % LL, b = tok / LL;
    float acc = cb[d];
    #pragma unroll
    for (int j=0;j<4;j++){
        int li = l - 3 + j;
        if (li >= 0)
            acc = fmaf(cw[d*4+j], __bfloat162float(xz[(size_t)(b*LL+li)*(2*DI) + d]), acc);
    }
    xc[idx] = __float2bfloat16(acc * sigmoidf_(acc));
}

// =====================================================================
// Fused single-pass selective scan with decoupled lookback.
// Block (bdb, seg): 16 channels x 64 steps.  In-kernel delta:
// delta = softplus(dbc[:, :48] . dt_w[d] + dt_b[d])   (fp32 dot, K=48).
// Pass A: segment summary (A_seg = prod dA, B_seg = h from h0=0) ->
// publish per-lane with release flag.  Lookback: spin on <=15 predecessor
// flags (strictly lower blockIdx => scheduled no later), chain h0.
// Pass B: replay segment from smem (no global reload), gate, store fp8.
// =====================================================================
__global__ void __launch_bounds__(256)
scan_fused_kernel(const float* __restrict__ dbc, const bf16* __restrict__ xc,
                  const bf16* __restrict__ xz,
                  const float* __restrict__ dtw, const float* __restrict__ dtb,
                  const float* __restrict__ A_log, const float* __restrict__ Dp,
                  float* __restrict__ sumA, float* __restrict__ sumB,
                  int* __restrict__ flags, fp8* __restrict__ out)
{
    __shared__ float s_w[16][DD];        // dt weights, fp32
    __shared__ float s_d48[SEGL][49];    // dbc[:, :48], padded stride 49
    __shared__ float s_delta[SEGL][16];
    __shared__ float s_x[SEGL][16];
    __shared__ float s_z[SEGL][16];
    __shared__ float s_B[SEGL][16];
    __shared__ float s_C[SEGL][16];

    int tid  = threadIdx.x;
    int bdb  = blockIdx.x % NGB;
    int seg  = blockIdx.x / NGB;
    int gg   = bdb*16 + (tid>>4);
    int n    = tid & 15;
    int b    = gg / DI;
    int d    = gg % DI;
    int d0   = (bdb*16) % DI;
    int t0   = seg * SEGL;

    // ---- loads ----
    int lj = tid & 15, lt0 = tid >> 4;
    #pragma unroll
    for (int k=0;k<4;k++){
        int t = lt0 + k*16;
        int tok = b*LL + t0 + t;
        s_x[t][lj] = __bfloat162float(xc[(size_t)tok*DI + d0 + lj]);
        s_z[t][lj] = __bfloat162float(xz[(size_t)tok*(2*DI) + DI + d0 + lj]);
        s_B[t][lj] = dbc[(size_t)tok*XPE + DD + lj];
        s_C[t][lj] = dbc[(size_t)tok*XPE + DD + DS + lj];
    }
    // d48: 64 tokens x 12 float4
    #pragma unroll
    for (int i=0;i<3;i++){
        int q = tid + i*256;          // < 768
        int t = q / 12, j = q % 12;
        float4 v = *(const float4*)(dbc + (size_t)(b*LL + t0 + t)*XPE + j*4);
        s_d48[t][j*4+0]=v.x; s_d48[t][j*4+1]=v.y; s_d48[t][j*4+2]=v.z; s_d48[t][j*4+3]=v.w;
    }
    // dt weights: 16 x 12 float4 = 192 loads
    if (tid < 192){
        int dj = tid / 12, j = tid % 12;
        float4 v = *(const float4*)(dtw + (size_t)(d0+dj)*DD + j*4);
        s_w[dj][j*4+0]=v.x; s_w[dj][j*4+1]=v.y; s_w[dj][j*4+2]=v.z; s_w[dj][j*4+3]=v.w;
    }

    float An = -expf(A_log[d*DS + n]);
    float Dd = Dp[d];
    __syncthreads();

    // ---- delta = softplus(d48 . w + bias), 4 elements per thread ----
    {
        int t  = tid >> 2;
        int djb = (tid & 3) * 4;
        float a0 = dtb[d0+djb], a1 = dtb[d0+djb+1], a2 = dtb[d0+djb+2], a3 = dtb[d0+djb+3];
        #pragma unroll
        for (int k=0;k<DD;k++){
            float dv = s_d48[t][k];
            a0 = fmaf(dv, s_w[djb  ][k], a0);
            a1 = fmaf(dv, s_w[djb+1][k], a1);
            a2 = fmaf(dv, s_w[djb+2][k], a2);
            a3 = fmaf(dv, s_w[djb+3][k], a3);
        }
        s_delta[t][djb]   = softplus_(a0);
        s_delta[t][djb+1] = softplus_(a1);
        s_delta[t][djb+2] = softplus_(a2);
        s_delta[t][djb+3] = softplus_(a3);
    }
    __syncthreads();

    int dj = tid >> 4;
    int L  = bdb*256 + tid;    // lane id (== gg*16 + n)

    // ---- pass A: segment summary ----
    float hs = 0.f, Ap = 1.f;
    #pragma unroll 4
    for (int t=0;t<SEGL;t++){
        float dlt = s_delta[t][dj];
        float dA  = __expf(dlt*An);
        Ap *= dA;
        hs = fmaf(dA, hs, dlt*s_B[t][n]*s_x[t][dj]);
    }
    sumA[seg*LANES + L] = Ap;
    sumB[seg*LANES + L] = hs;
    __threadfence();
    *(volatile int*)(flags + seg*LANES + L) = 1;

    // ---- lookback: chain predecessor summaries ----
    float h = 0.f;
    for (int s=0; s<seg; s++){
        volatile int* fl = flags + s*LANES + L;
        while (*fl == 0) {}
        __threadfence();
        float A_ = __ldcv(sumA + s*LANES + L);
        float B_ = __ldcv(sumB + s*LANES + L);
        h = fmaf(A_, h, B_);
    }

    // ---- pass B: replay with exact h0, reduce, gate, store ----
    #pragma unroll 4
    for (int t=0;t<SEGL;t++){
        float dlt = s_delta[t][dj];
        float xv  = s_x[t][dj];
        float dA  = __expf(dlt*An);
        h = fmaf(dA, h, dlt*s_B[t][n]*xv);
        float y = h*s_C[t][n];
        y += __shfl_xor_sync(0xffffffffu, y, 1);
        y += __shfl_xor_sync(0xffffffffu, y, 2);
        y += __shfl_xor_sync(0xffffffffu, y, 4);
        y += __shfl_xor_sync(0xffffffffu, y, 8);
        if (n == 0){
            float z  = s_z[t][dj];
            float sv = y + Dd*xv;
            out[(size_t)(b*LL + t0 + t)*DI + d] =
                f2e4(sv * z * (1.f/(1.f+__expf(-z))));
        }
    }
}

// ---------------- launcher ----------------
extern "C" void kernel_launch(void* const* d_in, const int* in_sizes, int n_in,
                              void* d_out, int out_size)
{
    const float* x       = (const float*)d_in[0];
    const float* in_w    = (const float*)d_in[1];
    const float* conv_w  = (const float*)d_in[2];
    const float* conv_b  = (const float*)d_in[3];
    const float* xproj_w = (const float*)d_in[4];
    const float* dt_w    = (const float*)d_in[5];
    const float* dt_b    = (const float*)d_in[6];
    const float* A_log   = (const float*)d_in[7];
    const float* Dp      = (const float*)d_in[8];
    const float* out_w   = (const float*)d_in[9];
    const float* norm_w  = (const float*)d_in[10];
    float* res = (float*)d_out;

    fp8 *xn, *y, *inw8, *ow8;
    bf16 *xz, *xc, *xpw;
    float *dbc, *sumA, *sumB;
    int *flags;
    cudaGetSymbolAddress((void**)&xn,    g8_xn);
    cudaGetSymbolAddress((void**)&xz,    gb_xz);
    cudaGetSymbolAddress((void**)&xc,    gb_xc);
    cudaGetSymbolAddress((void**)&dbc,   g_dbc);
    cudaGetSymbolAddress((void**)&y,     g8_y);
    cudaGetSymbolAddress((void**)&sumA,  g_sumA);
    cudaGetSymbolAddress((void**)&sumB,  g_sumB);
    cudaGetSymbolAddress((void**)&flags, g_flags);
    cudaGetSymbolAddress((void**)&inw8,  g8_inw);
    cudaGetSymbolAddress((void**)&ow8,   g8_ow);
    cudaGetSymbolAddress((void**)&xpw,   gb_xpw);

    const int GSMEM = 49152;
    cudaFuncSetAttribute(gemm_cp<3,1,false>, cudaFuncAttributeMaxDynamicSharedMemorySize, GSMEM);
    cudaFuncSetAttribute(gemm_cp<1,1,false>, cudaFuncAttributeMaxDynamicSharedMemorySize, GSMEM);
    cudaFuncSetAttribute(gemm_cp<1,2,true>,  cudaFuncAttributeMaxDynamicSharedMemorySize, GSMEM);

    // residual stream lives in d_out
    cudaMemcpyAsync(res, x, (size_t)NTOK*DM*sizeof(float), cudaMemcpyDeviceToDevice, 0);

    // weight converts (2 kernels -> in_proj gemm is kernel #4)
    {
        int na = 2*2*DI*DM, nb = 2*DM*DI;
        wq2_kernel<<<((na+nb)/4+255)/256, 256>>>(in_w, inw8, na, out_w, ow8, nb);
    }
    {
        int n = 2*XPE*DI;
        f2bf_kernel<<<(n/4+255)/256, 256>>>(xproj_w, xpw, n);
    }

    for (int l=0;l<2;l++){
        rmsnorm_kernel<<<NTOK, 256>>>(res, norm_w + l*DM, xn);

        // xz = (xn @ in_w^T)/64  (fp8 cp.async gemm, bf16 store)  <- kernel #4 on l=0
        gemm_cp<3,1,false><<<dim3(2*DI/128, NTOK/128, 1), 256, GSMEM>>>(
            xn, inw8 + (size_t)l*2*DI*DM, xz,
            NTOK, 2*DI, DM, DM, DM, 2*DI);

        conv_silu_kernel<<<(NTOK*DI)/256, 256>>>(xz, conv_w + l*DI*4, conv_b + l*DI,
                                                 xc, dbc, flags);

        // dbc = xc @ xproj_w^T  (bf16 cp.async gemm, split-K=8, atomics)
        gemm_cp<1,2,true><<<dim3(1, NTOK/128, 8), 256, GSMEM>>>(
            (const uint8_t*)xc, (const uint8_t*)(xpw + (size_t)l*XPE*DI), dbc,
            NTOK, XPE, (DI/8)*2, DI*2, DI*2, XPE);

        // fused scan (in-kernel dt projection + decoupled lookback)
        scan_fused_kernel<<<NGB*NSEG, 256>>>(dbc, xc, xz,
                                             dt_w + (size_t)l*DI*DD, dt_b + l*DI,
                                             A_log + (size_t)l*DI*DS, Dp + l*DI,
                                             sumA, sumB, flags, y);

        // res += (y @ out_w^T)/64  (fp8, split-K=3 => one full wave)
        gemm_cp<1,1,false><<<dim3(DM/128, NTOK/128, 3), 256, GSMEM>>>(
            y, ow8 + (size_t)l*DM*DI, res,
            NTOK, DM, DI/3, DI, DI, DM);
    }
}

// round 15
// speedup vs baseline: 1.0116x; 1.0116x over previous
#include <cuda_runtime.h>
#include <cuda_bf16.h>
#include <cuda_fp8.h>
#include <math.h>
#include <cstdint>

#define BB 2
#define LL 1024
#define DM 768
#define DI 1536
#define DS 16
#define DD 48
#define NTOK (BB*LL)
#define XPE 80   // D_DELTA + 2*D_STATE

#define NSEG 16
#define SEGL 64
#define NGB  (BB*DI/16)      // 192
#define LANES (BB*DI*DS)     // 49152

typedef __nv_bfloat16 bf16;
typedef uint8_t fp8;

#define WSCALE     64.0f
#define WSCALE_INV 0.015625f

// ---------------- scratch ----------------
__device__ fp8   g8_xn[NTOK*DM];
__device__ bf16  gb_xz[NTOK*2*DI];
__device__ bf16  gb_xc[NTOK*DI];
__device__ float g_dbc[NTOK*XPE];
__device__ float g_delta[NTOK*DI];
__device__ fp8   g8_y[NTOK*DI];
__device__ float g_sumA[NSEG*LANES];
__device__ float g_sumB[NSEG*LANES];
__device__ fp8   g8_inw[2*2*DI*DM];
__device__ fp8   g8_ow [2*DM*DI];
__device__ bf16  gb_xpw[2*XPE*DI];

__device__ __forceinline__ float sigmoidf_(float x){ return 1.f/(1.f+__expf(-x)); }
__device__ __forceinline__ float softplus_(float v){ return v > 20.f ? v : log1pf(expf(v)); }
__device__ __forceinline__ fp8 f2e4(float x){
    return (fp8)__nv_cvt_float_to_fp8(x, __NV_SATFINITE, __NV_E4M3);
}
__device__ __forceinline__ uint32_t pkbf(float a, float b){
    __nv_bfloat162 t = __floats2bfloat162_rn(a, b);
    return *(uint32_t*)&t;
}
__device__ __forceinline__ uint32_t smem_u32(const void* p){
    uint32_t a; asm("{ .reg .u64 t; cvta.to.shared.u64 t, %1; cvt.u32.u64 %0, t; }" : "=r"(a) : "l"(p));
    return a;
}

// ---------------- weight converts (2 kernels) ----------------
__global__ void wq2_kernel(const float* __restrict__ a, fp8* __restrict__ ao, int na,
                           const float* __restrict__ b, fp8* __restrict__ bo, int nb)
{
    int i = (blockIdx.x*256 + threadIdx.x)*4;
    const float* src; fp8* dst; int off;
    if (i < na)            { src = a; dst = ao; off = i; }
    else if (i < na + nb)  { src = b; dst = bo; off = i - na; }
    else return;
    float4 v = *(const float4*)(src + off);
    *(uint32_t*)(dst + off) = (uint32_t)f2e4(v.x*WSCALE)
        | ((uint32_t)f2e4(v.y*WSCALE)<<8) | ((uint32_t)f2e4(v.z*WSCALE)<<16)
        | ((uint32_t)f2e4(v.w*WSCALE)<<24);
}
__global__ void f2bf_kernel(const float* __restrict__ a, bf16* __restrict__ ao, int n)
{
    int i = (blockIdx.x*256 + threadIdx.x)*4;
    if (i >= n) return;
    float4 v = *(const float4*)(a + i);
    *(uint32_t*)(ao + i)   = pkbf(v.x, v.y);
    *(uint32_t*)(ao + i+2) = pkbf(v.z, v.w);
}

// ---------------- rmsnorm ----------------
__global__ void rmsnorm_kernel(const float* __restrict__ x, const float* __restrict__ w,
                               fp8* __restrict__ out)
{
    int tok = blockIdx.x;
    int tid = threadIdx.x;
    const float* xr = x + (size_t)tok*DM;
    float v0 = xr[tid], v1 = xr[tid+256], v2 = xr[tid+512];
    float s = v0*v0 + v1*v1 + v2*v2;
    #pragma unroll
    for (int o=16;o>0;o>>=1) s += __shfl_xor_sync(0xffffffffu, s, o);
    __shared__ float red[8];
    if ((tid&31)==0) red[tid>>5] = s;
    __syncthreads();
    float tot = red[0]+red[1]+red[2]+red[3]+red[4]+red[5]+red[6]+red[7];
    float r = rsqrtf(tot * (1.f/768.f) + 1e-5f);
    fp8* o = out + (size_t)tok*DM;
    o[tid]     = f2e4(w[tid]     * v0 * r);
    o[tid+256] = f2e4(w[tid+256] * v1 * r);
    o[tid+512] = f2e4(w[tid+512] * v2 * r);
}

// =====================================================================
// cp.async + ldmatrix tensor GEMM (R10/R12-proven, unchanged).
// =====================================================================
template<int EPI, int ESZ, bool NGUARD>
__global__ void __launch_bounds__(256, 2)
gemm_cp(const uint8_t* __restrict__ A, const uint8_t* __restrict__ B,
        void* __restrict__ Cv, int M, int N, int KlenB,
        int ldaB, int ldbB, int ldc)
{
    extern __shared__ uint8_t smem[];
    uint32_t sbase = smem_u32(smem);

    int tid = threadIdx.x;
    int lane = tid & 31;
    int w    = tid >> 5;
    int wm   = w & 1;
    int wn   = w >> 1;
    int m0 = blockIdx.y * 128;
    int n0 = blockIdx.x * 128;
    int kbegB = blockIdx.z * KlenB;

    const uint8_t* Agb = A + (size_t)m0*ldaB + kbegB;
    const uint8_t* Bgb = B + (size_t)n0*ldbB + kbegB;

    auto a_off = [](int r, int cx)->uint32_t {
        uint32_t c8 = (uint32_t)((((r&1)<<2) + cx) ^ ((r>>1)&7));
        return (uint32_t)((r>>1)*128) + c8*16;
    };

    const int KT = KlenB / 64;

    auto issue = [&](int kt){
        if (kt < KT){
            uint32_t st = sbase + (uint32_t)(kt%3)*16384u;
            #pragma unroll
            for (int i=0;i<2;i++){
                int q = tid + i*256;
                int r = q >> 2, cx = q & 3;
                const uint8_t* ga = Agb + (size_t)r*ldaB + kt*64 + cx*16;
                uint32_t da = st + a_off(r, cx);
                asm volatile("cp.async.cg.shared.global [%0], [%1], 16;" :: "r"(da), "l"(ga));
                int rb = (NGUARD && (n0 + r >= N)) ? 0 : r;
                const uint8_t* gb = Bgb + (size_t)rb*ldbB + kt*64 + cx*16;
                uint32_t db = st + 8192u + a_off(r, cx);
                if (NGUARD){
                    unsigned ssz = (n0 + r < N) ? 16u : 0u;
                    asm volatile("cp.async.cg.shared.global [%0], [%1], 16, %2;" :: "r"(db), "l"(gb), "r"(ssz));
                } else {
                    asm volatile("cp.async.cg.shared.global [%0], [%1], 16;" :: "r"(db), "l"(gb));
                }
            }
        }
        asm volatile("cp.async.commit_group;");
    };

    float acc[4][4][4];
    #pragma unroll
    for (int i=0;i<4;i++)
        #pragma unroll
        for (int j=0;j<4;j++)
            #pragma unroll
            for (int e=0;e<4;e++) acc[i][j][e]=0.f;

    issue(0);
    issue(1);

    int mi   = lane >> 3;
    int lrow = lane & 7;

    for (int kt=0; kt<KT; kt++){
        asm volatile("cp.async.wait_group 1;" ::: "memory");
        __syncthreads();
        issue(kt+2);

        uint32_t st = sbase + (uint32_t)(kt%3)*16384u;
        #pragma unroll
        for (int g2=0; g2<2; g2++){
            uint32_t av[4][4];
            #pragma unroll
            for (int i=0;i<4;i++){
                int row = wm*64 + i*16 + ((mi&1)<<3) + lrow;
                int cx  = 2*g2 + (mi>>1);
                uint32_t ad = st + a_off(row, cx);
                asm volatile("ldmatrix.sync.aligned.m8n8.x4.shared.b16 {%0,%1,%2,%3}, [%4];"
                    : "=r"(av[i][0]), "=r"(av[i][1]), "=r"(av[i][2]), "=r"(av[i][3])
                    : "r"(ad));
            }
            uint32_t bv[4][2];
            #pragma unroll
            for (int P=0; P<2; P++){
                int nrow = wn*32 + (2*P + (mi>>1))*8 + lrow;
                int cx   = 2*g2 + (mi&1);
                uint32_t bd = st + 8192u + a_off(nrow, cx);
                asm volatile("ldmatrix.sync.aligned.m8n8.x4.shared.b16 {%0,%1,%2,%3}, [%4];"
                    : "=r"(bv[2*P][0]), "=r"(bv[2*P][1]), "=r"(bv[2*P+1][0]), "=r"(bv[2*P+1][1])
                    : "r"(bd));
            }
            #pragma unroll
            for (int i=0;i<4;i++)
                #pragma unroll
                for (int j=0;j<4;j++){
                    if (ESZ == 1){
                        asm volatile(
                            "mma.sync.aligned.m16n8k32.row.col.f32.e4m3.e4m3.f32 "
                            "{%0,%1,%2,%3}, {%4,%5,%6,%7}, {%8,%9}, {%0,%1,%2,%3};"
                            : "+f"(acc[i][j][0]), "+f"(acc[i][j][1]),
                              "+f"(acc[i][j][2]), "+f"(acc[i][j][3])
                            : "r"(av[i][0]), "r"(av[i][1]), "r"(av[i][2]), "r"(av[i][3]),
                              "r"(bv[j][0]), "r"(bv[j][1]));
                    } else {
                        asm volatile(
                            "mma.sync.aligned.m16n8k16.row.col.f32.bf16.bf16.f32 "
                            "{%0,%1,%2,%3}, {%4,%5,%6,%7}, {%8,%9}, {%0,%1,%2,%3};"
                            : "+f"(acc[i][j][0]), "+f"(acc[i][j][1]),
                              "+f"(acc[i][j][2]), "+f"(acc[i][j][3])
                            : "r"(av[i][0]), "r"(av[i][1]), "r"(av[i][2]), "r"(av[i][3]),
                              "r"(bv[j][0]), "r"(bv[j][1]));
                    }
                }
        }
        __syncthreads();
    }

    const float SCL = (ESZ == 1) ? WSCALE_INV : 1.0f;
    float* C  = (float*)Cv;
    bf16*  Cb = (bf16*)Cv;
    int g4c = lane >> 2, tc = lane & 3;
    #pragma unroll
    for (int i=0;i<4;i++){
        int row = m0 + (wm*4 + i)*16 + g4c;
        #pragma unroll
        for (int j=0;j<4;j++){
            int col = n0 + (wn*4 + j)*8 + tc*2;
            if (NGUARD && col >= N) continue;
            float v0 = acc[i][j][0]*SCL, v1 = acc[i][j][1]*SCL;
            float v2 = acc[i][j][2]*SCL, v3 = acc[i][j][3]*SCL;
            if (EPI == 1){
                float* cp0 = C + (size_t)row*ldc + col;
                float* cp1 = C + (size_t)(row+8)*ldc + col;
                atomicAdd(cp0,   v0);
                atomicAdd(cp0+1, v1);
                atomicAdd(cp1,   v2);
                atomicAdd(cp1+1, v3);
            } else {
                *(__nv_bfloat162*)(Cb + (size_t)row*ldc + col)     = __floats2bfloat162_rn(v0, v1);
                *(__nv_bfloat162*)(Cb + (size_t)(row+8)*ldc + col) = __floats2bfloat162_rn(v2, v3);
            }
        }
    }
}

// ---------------- conv + SiLU; also zeroes dbc ----------------
__global__ void conv_silu_kernel(const bf16* __restrict__ xz, const float* __restrict__ cw,
                                 const float* __restrict__ cb, bf16* __restrict__ xc,
                                 float* __restrict__ dbc)
{
    int idx = blockIdx.x*blockDim.x + threadIdx.x;
    if (idx < NTOK*XPE) dbc[idx] = 0.f;
    int d = idx % DI;
    int tok = idx / DI;
    int l = tok % LL, b = tok / LL;
    float acc = cb[d];
    #pragma unroll
    for (int j=0;j<4;j++){
        int li = l - 3 + j;
        if (li >= 0)
            acc = fmaf(cw[d*4+j], __bfloat162float(xz[(size_t)(b*LL+li)*(2*DI) + d]), acc);
    }
    xc[idx] = __float2bfloat16(acc * sigmoidf_(acc));
}

// =====================================================================
// Scan pass 1 + fused dt projection.
// delta = softplus(dbc[:,:48] . dt_w[d] + dt_b[d]) computed in smem
// (fp32, validated in R13), used for the segment summary, and written
// to the global delta buffer for pass 2.  No inter-block sync.
// =====================================================================
__global__ void __launch_bounds__(256)
scan_sum_kernel(const float* __restrict__ dbc, const bf16* __restrict__ xc,
                const float* __restrict__ dtw, const float* __restrict__ dtb,
                const float* __restrict__ A_log,
                float* __restrict__ delta_out,
                float* __restrict__ sumA, float* __restrict__ sumB)
{
    __shared__ float s_w[16][DD];
    __shared__ float s_d48[SEGL][49];
    __shared__ float s_delta[SEGL][16];
    __shared__ float s_x[SEGL][16];
    __shared__ float s_B[SEGL][16];

    int tid  = threadIdx.x;
    int bdb  = blockIdx.x % NGB;
    int seg  = blockIdx.x / NGB;
    int gg   = bdb*16 + (tid>>4);
    int n    = tid & 15;
    int b    = gg / DI;
    int d    = gg % DI;
    int d0   = (bdb*16) % DI;
    int t0   = seg * SEGL;

    int lj = tid & 15, lt0 = tid >> 4;
    #pragma unroll
    for (int k=0;k<4;k++){
        int t = lt0 + k*16;
        int tok = b*LL + t0 + t;
        s_x[t][lj] = __bfloat162float(xc[(size_t)tok*DI + d0 + lj]);
        s_B[t][lj] = dbc[(size_t)tok*XPE + DD + lj];
    }
    #pragma unroll
    for (int i=0;i<3;i++){
        int q = tid + i*256;          // < 768
        int t = q / 12, j = q % 12;
        float4 v = *(const float4*)(dbc + (size_t)(b*LL + t0 + t)*XPE + j*4);
        s_d48[t][j*4+0]=v.x; s_d48[t][j*4+1]=v.y; s_d48[t][j*4+2]=v.z; s_d48[t][j*4+3]=v.w;
    }
    if (tid < 192){
        int dj = tid / 12, j = tid % 12;
        float4 v = *(const float4*)(dtw + (size_t)(d0+dj)*DD + j*4);
        s_w[dj][j*4+0]=v.x; s_w[dj][j*4+1]=v.y; s_w[dj][j*4+2]=v.z; s_w[dj][j*4+3]=v.w;
    }
    float An = -expf(A_log[d*DS + n]);
    __syncthreads();

    // delta dot: 4 output elements per thread
    {
        int t   = tid >> 2;
        int djb = (tid & 3) * 4;
        float a0 = dtb[d0+djb], a1 = dtb[d0+djb+1], a2 = dtb[d0+djb+2], a3 = dtb[d0+djb+3];
        #pragma unroll
        for (int k=0;k<DD;k++){
            float dv = s_d48[t][k];
            a0 = fmaf(dv, s_w[djb  ][k], a0);
            a1 = fmaf(dv, s_w[djb+1][k], a1);
            a2 = fmaf(dv, s_w[djb+2][k], a2);
            a3 = fmaf(dv, s_w[djb+3][k], a3);
        }
        float d0v = softplus_(a0), d1v = softplus_(a1);
        float d2v = softplus_(a2), d3v = softplus_(a3);
        s_delta[t][djb]   = d0v;
        s_delta[t][djb+1] = d1v;
        s_delta[t][djb+2] = d2v;
        s_delta[t][djb+3] = d3v;
        float* dp = delta_out + (size_t)(b*LL + t0 + t)*DI + d0 + djb;
        *(float4*)dp = make_float4(d0v, d1v, d2v, d3v);
    }
    __syncthreads();

    int dj = tid >> 4;
    float h = 0.f, Ap = 1.f;
    #pragma unroll 4
    for (int t=0;t<SEGL;t++){
        float dlt = s_delta[t][dj];
        float dA  = __expf(dlt*An);
        Ap *= dA;
        h = fmaf(dA, h, dlt*s_B[t][n]*s_x[t][dj]);
    }
    int L = gg*16 + n;
    sumA[seg*LANES + L] = Ap;
    sumB[seg*LANES + L] = h;
}

// ---------------- scan pass 2 (R12-proven, unchanged) ----------------
__global__ void __launch_bounds__(256)
scan_apply_kernel(const float* __restrict__ delta, const bf16* __restrict__ xc,
                  const float* __restrict__ dbc, const bf16* __restrict__ xz,
                  const float* __restrict__ A_log, const float* __restrict__ Dp,
                  const float* __restrict__ sumA, const float* __restrict__ sumB,
                  fp8* __restrict__ out)
{
    __shared__ float s_delta[SEGL][16];
    __shared__ float s_x[SEGL][16];
    __shared__ float s_z[SEGL][16];
    __shared__ float s_B[SEGL][16];
    __shared__ float s_C[SEGL][16];

    int tid  = threadIdx.x;
    int bdb  = blockIdx.x % NGB;
    int seg  = blockIdx.x / NGB;
    int gg   = bdb*16 + (tid>>4);
    int n    = tid & 15;
    int b    = gg / DI;
    int d    = gg % DI;
    int d0   = (bdb*16) % DI;
    int t0   = seg * SEGL;

    int lj = tid & 15, lt0 = tid >> 4;
    #pragma unroll
    for (int k=0;k<4;k++){
        int t = lt0 + k*16;
        int tok = b*LL + t0 + t;
        s_delta[t][lj] = delta[(size_t)tok*DI + d0 + lj];
        s_x[t][lj]     = __bfloat162float(xc[(size_t)tok*DI + d0 + lj]);
        s_z[t][lj]     = __bfloat162float(xz[(size_t)tok*(2*DI) + DI + d0 + lj]);
        s_B[t][lj]     = dbc[(size_t)tok*XPE + DD + lj];
        s_C[t][lj]     = dbc[(size_t)tok*XPE + DD + DS + lj];
    }

    float An = -expf(A_log[d*DS + n]);
    float Dd = Dp[d];

    int L = gg*16 + n;
    float h = 0.f;
    for (int s=0; s<seg; s++)
        h = fmaf(sumA[s*LANES + L], h, sumB[s*LANES + L]);

    __syncthreads();

    int dj = tid >> 4;
    #pragma unroll 4
    for (int t=0;t<SEGL;t++){
        float dlt = s_delta[t][dj];
        float xv  = s_x[t][dj];
        float dA  = __expf(dlt*An);
        h = fmaf(dA, h, dlt*s_B[t][n]*xv);
        float y = h*s_C[t][n];
        y += __shfl_xor_sync(0xffffffffu, y, 1);
        y += __shfl_xor_sync(0xffffffffu, y, 2);
        y += __shfl_xor_sync(0xffffffffu, y, 4);
        y += __shfl_xor_sync(0xffffffffu, y, 8);
        if (n == 0){
            float z  = s_z[t][dj];
            float sv = y + Dd*xv;
            out[(size_t)(b*LL + t0 + t)*DI + d] =
                f2e4(sv * z * (1.f/(1.f+__expf(-z))));
        }
    }
}

// ---------------- launcher ----------------
extern "C" void kernel_launch(void* const* d_in, const int* in_sizes, int n_in,
                              void* d_out, int out_size)
{
    const float* x       = (const float*)d_in[0];
    const float* in_w    = (const float*)d_in[1];
    const float* conv_w  = (const float*)d_in[2];
    const float* conv_b  = (const float*)d_in[3];
    const float* xproj_w = (const float*)d_in[4];
    const float* dt_w    = (const float*)d_in[5];
    const float* dt_b    = (const float*)d_in[6];
    const float* A_log   = (const float*)d_in[7];
    const float* Dp      = (const float*)d_in[8];
    const float* out_w   = (const float*)d_in[9];
    const float* norm_w  = (const float*)d_in[10];
    float* res = (float*)d_out;

    fp8 *xn, *y, *inw8, *ow8;
    bf16 *xz, *xc, *xpw;
    float *dbc, *delta, *sumA, *sumB;
    cudaGetSymbolAddress((void**)&xn,    g8_xn);
    cudaGetSymbolAddress((void**)&xz,    gb_xz);
    cudaGetSymbolAddress((void**)&xc,    gb_xc);
    cudaGetSymbolAddress((void**)&dbc,   g_dbc);
    cudaGetSymbolAddress((void**)&delta, g_delta);
    cudaGetSymbolAddress((void**)&y,     g8_y);
    cudaGetSymbolAddress((void**)&sumA,  g_sumA);
    cudaGetSymbolAddress((void**)&sumB,  g_sumB);
    cudaGetSymbolAddress((void**)&inw8,  g8_inw);
    cudaGetSymbolAddress((void**)&ow8,   g8_ow);
    cudaGetSymbolAddress((void**)&xpw,   gb_xpw);

    const int GSMEM = 49152;
    cudaFuncSetAttribute(gemm_cp<3,1,false>, cudaFuncAttributeMaxDynamicSharedMemorySize, GSMEM);
    cudaFuncSetAttribute(gemm_cp<1,1,false>, cudaFuncAttributeMaxDynamicSharedMemorySize, GSMEM);
    cudaFuncSetAttribute(gemm_cp<1,2,true>,  cudaFuncAttributeMaxDynamicSharedMemorySize, GSMEM);

    // residual stream lives in d_out
    cudaMemcpyAsync(res, x, (size_t)NTOK*DM*sizeof(float), cudaMemcpyDeviceToDevice, 0);

    // weight converts (2 kernels -> in_proj gemm is kernel #4)
    {
        int na = 2*2*DI*DM, nb = 2*DM*DI;
        wq2_kernel<<<((na+nb)/4+255)/256, 256>>>(in_w, inw8, na, out_w, ow8, nb);
    }
    {
        int n = 2*XPE*DI;
        f2bf_kernel<<<(n/4+255)/256, 256>>>(xproj_w, xpw, n);
    }

    for (int l=0;l<2;l++){
        rmsnorm_kernel<<<NTOK, 256>>>(res, norm_w + l*DM, xn);

        // xz = (xn @ in_w^T)/64  (fp8 cp.async gemm, bf16 store)  <- kernel #4 on l=0
        gemm_cp<3,1,false><<<dim3(2*DI/128, NTOK/128, 1), 256, GSMEM>>>(
            xn, inw8 + (size_t)l*2*DI*DM, xz,
            NTOK, 2*DI, DM, DM, DM, 2*DI);

        conv_silu_kernel<<<(NTOK*DI)/256, 256>>>(xz, conv_w + l*DI*4, conv_b + l*DI,
                                                 xc, dbc);

        // dbc = xc @ xproj_w^T  (bf16 cp.async gemm, split-K=8, atomics)
        gemm_cp<1,2,true><<<dim3(1, NTOK/128, 8), 256, GSMEM>>>(
            (const uint8_t*)xc, (const uint8_t*)(xpw + (size_t)l*XPE*DI), dbc,
            NTOK, XPE, (DI/8)*2, DI*2, DI*2, XPE);

        // scan pass 1 with fused dt projection (writes delta + summaries)
        scan_sum_kernel<<<NGB*NSEG, 256>>>(dbc, xc,
                                           dt_w + (size_t)l*DI*DD, dt_b + l*DI,
                                           A_log + (size_t)l*DI*DS,
                                           delta, sumA, sumB);

        // scan pass 2
        scan_apply_kernel<<<NGB*NSEG, 256>>>(delta, xc, dbc, xz,
                                             A_log + (size_t)l*DI*DS, Dp + l*DI,
                                             sumA, sumB, y);

        // res += (y @ out_w^T)/64  (fp8, split-K=3 => one full wave)
        gemm_cp<1,1,false><<<dim3(DM/128, NTOK/128, 3), 256, GSMEM>>>(
            y, ow8 + (size_t)l*DM*DI, res,
            NTOK, DM, DI/3, DI, DI, DM);
    }
}

// round 16
// speedup vs baseline: 1.3561x; 1.3405x over previous
#include <cuda_runtime.h>
#include <cuda_bf16.h>
#include <cuda_fp8.h>
#include <math.h>
#include <cstdint>

#define BB 2
#define LL 1024
#define DM 768
#define DI 1536
#define DS 16
#define DD 48
#define NTOK (BB*LL)
#define XPE 80   // D_DELTA + 2*D_STATE

#define NSEG 16
#define SEGL 64
#define NGB  (BB*DI/16)      // 192
#define LANES (BB*DI*DS)     // 49152

typedef __nv_bfloat16 bf16;
typedef uint8_t fp8;

#define WSCALE     64.0f
#define WSCALE_INV 0.015625f

// ---------------- scratch ----------------
__device__ fp8   g8_xn[NTOK*DM];
__device__ bf16  gb_xz[NTOK*2*DI];
__device__ bf16  gb_xc[NTOK*DI];
__device__ float g_dbc[NTOK*XPE];
__device__ float g_delta[NTOK*DI];
__device__ fp8   g8_y[NTOK*DI];
__device__ float g_sumA[NSEG*LANES];
__device__ float g_sumB[NSEG*LANES];
__device__ fp8   g8_inw[2*2*DI*DM];
__device__ fp8   g8_ow [2*DM*DI];
__device__ bf16  gb_xpw[2*XPE*DI];
__device__ bf16  gb_dtw[2*DI*DD];

__device__ __forceinline__ float sigmoidf_(float x){ return 1.f/(1.f+__expf(-x)); }
__device__ __forceinline__ float softplus_(float v){ return v > 20.f ? v : log1pf(expf(v)); }
__device__ __forceinline__ fp8 f2e4(float x){
    return (fp8)__nv_cvt_float_to_fp8(x, __NV_SATFINITE, __NV_E4M3);
}
__device__ __forceinline__ uint32_t pkbf(float a, float b){
    __nv_bfloat162 t = __floats2bfloat162_rn(a, b);
    return *(uint32_t*)&t;
}
__device__ __forceinline__ uint32_t smem_u32(const void* p){
    uint32_t a; asm("{ .reg .u64 t; cvta.to.shared.u64 t, %1; cvt.u32.u64 %0, t; }" : "=r"(a) : "l"(p));
    return a;
}

// ---------------- weight converts (2 kernels) ----------------
__global__ void wq2_kernel(const float* __restrict__ a, fp8* __restrict__ ao, int na,
                           const float* __restrict__ b, fp8* __restrict__ bo, int nb)
{
    int i = (blockIdx.x*256 + threadIdx.x)*4;
    const float* src; fp8* dst; int off;
    if (i < na)            { src = a; dst = ao; off = i; }
    else if (i < na + nb)  { src = b; dst = bo; off = i - na; }
    else return;
    float4 v = *(const float4*)(src + off);
    *(uint32_t*)(dst + off) = (uint32_t)f2e4(v.x*WSCALE)
        | ((uint32_t)f2e4(v.y*WSCALE)<<8) | ((uint32_t)f2e4(v.z*WSCALE)<<16)
        | ((uint32_t)f2e4(v.w*WSCALE)<<24);
}
__global__ void f2bf2_kernel(const float* __restrict__ a, bf16* __restrict__ ao, int na,
                             const float* __restrict__ b, bf16* __restrict__ bo, int nb)
{
    int i = (blockIdx.x*256 + threadIdx.x)*4;
    const float* src; bf16* dst; int off;
    if (i < na)            { src = a; dst = ao; off = i; }
    else if (i < na + nb)  { src = b; dst = bo; off = i - na; }
    else return;
    float4 v = *(const float4*)(src + off);
    *(uint32_t*)(dst + off)   = pkbf(v.x, v.y);
    *(uint32_t*)(dst + off+2) = pkbf(v.z, v.w);
}

// ---------------- rmsnorm ----------------
__global__ void rmsnorm_kernel(const float* __restrict__ x, const float* __restrict__ w,
                               fp8* __restrict__ out)
{
    int tok = blockIdx.x;
    int tid = threadIdx.x;
    const float* xr = x + (size_t)tok*DM;
    float v0 = xr[tid], v1 = xr[tid+256], v2 = xr[tid+512];
    float s = v0*v0 + v1*v1 + v2*v2;
    #pragma unroll
    for (int o=16;o>0;o>>=1) s += __shfl_xor_sync(0xffffffffu, s, o);
    __shared__ float red[8];
    if ((tid&31)==0) red[tid>>5] = s;
    __syncthreads();
    float tot = red[0]+red[1]+red[2]+red[3]+red[4]+red[5]+red[6]+red[7];
    float r = rsqrtf(tot * (1.f/768.f) + 1e-5f);
    fp8* o = out + (size_t)tok*DM;
    o[tid]     = f2e4(w[tid]     * v0 * r);
    o[tid+256] = f2e4(w[tid+256] * v1 * r);
    o[tid+512] = f2e4(w[tid+512] * v2 * r);
}

// =====================================================================
// cp.async + ldmatrix tensor GEMM (R10/R12-proven, unchanged).
// Tile 128x128 x 64 BYTES, 8 warps (2m x 4n), 3-stage cp.async pipeline.
// ESZ=1: fp8 m16n8k32 (descale 1/64); ESZ=2: bf16 m16n8k16.
// EPI: 1 = atomicAdd fp32, 3 = store bf16.  NGUARD: B rows/C cols vs N.
// =====================================================================
template<int EPI, int ESZ, bool NGUARD>
__global__ void __launch_bounds__(256, 2)
gemm_cp(const uint8_t* __restrict__ A, const uint8_t* __restrict__ B,
        void* __restrict__ Cv, int M, int N, int KlenB,
        int ldaB, int ldbB, int ldc)
{
    extern __shared__ uint8_t smem[];
    uint32_t sbase = smem_u32(smem);

    int tid = threadIdx.x;
    int lane = tid & 31;
    int w    = tid >> 5;
    int wm   = w & 1;
    int wn   = w >> 1;
    int m0 = blockIdx.y * 128;
    int n0 = blockIdx.x * 128;
    int kbegB = blockIdx.z * KlenB;

    const uint8_t* Agb = A + (size_t)m0*ldaB + kbegB;
    const uint8_t* Bgb = B + (size_t)n0*ldbB + kbegB;

    auto a_off = [](int r, int cx)->uint32_t {
        uint32_t c8 = (uint32_t)((((r&1)<<2) + cx) ^ ((r>>1)&7));
        return (uint32_t)((r>>1)*128) + c8*16;
    };

    const int KT = KlenB / 64;

    auto issue = [&](int kt){
        if (kt < KT){
            uint32_t st = sbase + (uint32_t)(kt%3)*16384u;
            #pragma unroll
            for (int i=0;i<2;i++){
                int q = tid + i*256;
                int r = q >> 2, cx = q & 3;
                const uint8_t* ga = Agb + (size_t)r*ldaB + kt*64 + cx*16;
                uint32_t da = st + a_off(r, cx);
                asm volatile("cp.async.cg.shared.global [%0], [%1], 16;" :: "r"(da), "l"(ga));
                int rb = (NGUARD && (n0 + r >= N)) ? 0 : r;
                const uint8_t* gb = Bgb + (size_t)rb*ldbB + kt*64 + cx*16;
                uint32_t db = st + 8192u + a_off(r, cx);
                if (NGUARD){
                    unsigned ssz = (n0 + r < N) ? 16u : 0u;
                    asm volatile("cp.async.cg.shared.global [%0], [%1], 16, %2;" :: "r"(db), "l"(gb), "r"(ssz));
                } else {
                    asm volatile("cp.async.cg.shared.global [%0], [%1], 16;" :: "r"(db), "l"(gb));
                }
            }
        }
        asm volatile("cp.async.commit_group;");
    };

    float acc[4][4][4];
    #pragma unroll
    for (int i=0;i<4;i++)
        #pragma unroll
        for (int j=0;j<4;j++)
            #pragma unroll
            for (int e=0;e<4;e++) acc[i][j][e]=0.f;

    issue(0);
    issue(1);

    int mi   = lane >> 3;
    int lrow = lane & 7;

    for (int kt=0; kt<KT; kt++){
        asm volatile("cp.async.wait_group 1;" ::: "memory");
        __syncthreads();
        issue(kt+2);

        uint32_t st = sbase + (uint32_t)(kt%3)*16384u;
        #pragma unroll
        for (int g2=0; g2<2; g2++){
            uint32_t av[4][4];
            #pragma unroll
            for (int i=0;i<4;i++){
                int row = wm*64 + i*16 + ((mi&1)<<3) + lrow;
                int cx  = 2*g2 + (mi>>1);
                uint32_t ad = st + a_off(row, cx);
                asm volatile("ldmatrix.sync.aligned.m8n8.x4.shared.b16 {%0,%1,%2,%3}, [%4];"
                    : "=r"(av[i][0]), "=r"(av[i][1]), "=r"(av[i][2]), "=r"(av[i][3])
                    : "r"(ad));
            }
            uint32_t bv[4][2];
            #pragma unroll
            for (int P=0; P<2; P++){
                int nrow = wn*32 + (2*P + (mi>>1))*8 + lrow;
                int cx   = 2*g2 + (mi&1);
                uint32_t bd = st + 8192u + a_off(nrow, cx);
                asm volatile("ldmatrix.sync.aligned.m8n8.x4.shared.b16 {%0,%1,%2,%3}, [%4];"
                    : "=r"(bv[2*P][0]), "=r"(bv[2*P][1]), "=r"(bv[2*P+1][0]), "=r"(bv[2*P+1][1])
                    : "r"(bd));
            }
            #pragma unroll
            for (int i=0;i<4;i++)
                #pragma unroll
                for (int j=0;j<4;j++){
                    if (ESZ == 1){
                        asm volatile(
                            "mma.sync.aligned.m16n8k32.row.col.f32.e4m3.e4m3.f32 "
                            "{%0,%1,%2,%3}, {%4,%5,%6,%7}, {%8,%9}, {%0,%1,%2,%3};"
                            : "+f"(acc[i][j][0]), "+f"(acc[i][j][1]),
                              "+f"(acc[i][j][2]), "+f"(acc[i][j][3])
                            : "r"(av[i][0]), "r"(av[i][1]), "r"(av[i][2]), "r"(av[i][3]),
                              "r"(bv[j][0]), "r"(bv[j][1]));
                    } else {
                        asm volatile(
                            "mma.sync.aligned.m16n8k16.row.col.f32.bf16.bf16.f32 "
                            "{%0,%1,%2,%3}, {%4,%5,%6,%7}, {%8,%9}, {%0,%1,%2,%3};"
                            : "+f"(acc[i][j][0]), "+f"(acc[i][j][1]),
                              "+f"(acc[i][j][2]), "+f"(acc[i][j][3])
                            : "r"(av[i][0]), "r"(av[i][1]), "r"(av[i][2]), "r"(av[i][3]),
                              "r"(bv[j][0]), "r"(bv[j][1]));
                    }
                }
        }
        __syncthreads();
    }

    const float SCL = (ESZ == 1) ? WSCALE_INV : 1.0f;
    float* C  = (float*)Cv;
    bf16*  Cb = (bf16*)Cv;
    int g4c = lane >> 2, tc = lane & 3;
    #pragma unroll
    for (int i=0;i<4;i++){
        int row = m0 + (wm*4 + i)*16 + g4c;
        #pragma unroll
        for (int j=0;j<4;j++){
            int col = n0 + (wn*4 + j)*8 + tc*2;
            if (NGUARD && col >= N) continue;
            float v0 = acc[i][j][0]*SCL, v1 = acc[i][j][1]*SCL;
            float v2 = acc[i][j][2]*SCL, v3 = acc[i][j][3]*SCL;
            if (EPI == 1){
                float* cp0 = C + (size_t)row*ldc + col;
                float* cp1 = C + (size_t)(row+8)*ldc + col;
                atomicAdd(cp0,   v0);
                atomicAdd(cp0+1, v1);
                atomicAdd(cp1,   v2);
                atomicAdd(cp1+1, v3);
            } else {
                *(__nv_bfloat162*)(Cb + (size_t)row*ldc + col)     = __floats2bfloat162_rn(v0, v1);
                *(__nv_bfloat162*)(Cb + (size_t)(row+8)*ldc + col) = __floats2bfloat162_rn(v2, v3);
            }
        }
    }
}

// =====================================================================
// BF16 register-staging GEMM — dt (A fp32, K=48, softplus epi). R12-proven.
// =====================================================================
__global__ void __launch_bounds__(256, 2)
gemm_dt(const float* __restrict__ Af, const bf16* __restrict__ B,
        const float* __restrict__ bias, float* __restrict__ C,
        int M, int N, int Klen, int lda, int ldb, int ldc)
{
    __shared__ uint32_t sA[2][2048];
    __shared__ uint32_t sB[2][2048];

    int tid = threadIdx.x;
    int lane = tid & 31;
    int w    = tid >> 5;
    int wm   = w & 1;
    int wn   = w >> 1;
    int m0 = blockIdx.y * 128;
    int n0 = blockIdx.x * 128;

    int r  = tid >> 1;
    int g  = tid & 1;
    int kh = g * 16;

    const float* Agf = Af + (size_t)(m0 + r)*lda + kh;
    const bf16*  Bg  = B + (size_t)(n0 + r)*ldb + kh;

    int mt  = r >> 4;
    int g4  = r & 7;
    int rhi = (r >> 3) & 1;
    int nt  = r >> 3;

    uint32_t pa[8], pb[8];

    auto load_tile = [&](int kt){
        int kb = kt*32 + kh;
        uint4 z4 = make_uint4(0u,0u,0u,0u);
        if (kb < Klen){
            const float* p = Agf + kt*32;
            float4 f0 = *(const float4*)(p);
            float4 f1 = *(const float4*)(p+4);
            float4 f2 = *(const float4*)(p+8);
            float4 f3 = *(const float4*)(p+12);
            pa[0]=pkbf(f0.x,f0.y); pa[1]=pkbf(f0.z,f0.w);
            pa[2]=pkbf(f1.x,f1.y); pa[3]=pkbf(f1.z,f1.w);
            pa[4]=pkbf(f2.x,f2.y); pa[5]=pkbf(f2.z,f2.w);
            pa[6]=pkbf(f3.x,f3.y); pa[7]=pkbf(f3.z,f3.w);
        } else {
            #pragma unroll
            for (int p=0;p<8;p++) pa[p]=0u;
        }
        uint4 b0 = (kb     < Klen) ? *(const uint4*)(Bg + kt*32)     : z4;
        uint4 b1 = (kb + 8 < Klen) ? *(const uint4*)(Bg + kt*32 + 8) : z4;
        pb[0]=b0.x; pb[1]=b0.y; pb[2]=b0.z; pb[3]=b0.w;
        pb[4]=b1.x; pb[5]=b1.y; pb[6]=b1.z; pb[7]=b1.w;
    };

    float acc[4][4][4];
    #pragma unroll
    for (int i=0;i<4;i++)
        #pragma unroll
        for (int j=0;j<4;j++)
            #pragma unroll
            for (int e=0;e<4;e++) acc[i][j][e]=0.f;

    const int KT = (Klen + 31) / 32;
    load_tile(0);

    int lp = lane ^ ((lane>>3)&3);

    for (int kt=0; kt<KT; kt++){
        int st = kt & 1;

        #pragma unroll
        for (int p=0;p<8;p++){
            int t = p & 3, khi = p >> 2;
            int lA = g4*4 + t;  lA = lA ^ ((lA>>3)&3) ^ g;
            sA[st][((g*8  + mt)*32 + lA)*4 + rhi + 2*khi] = pa[p];
            int lB = g4*4 + t;  lB = lB ^ ((lB>>3)&3) ^ g ^ ((nt&1)<<1);
            sB[st][((g*16 + nt)*32 + lB)*2 + khi]         = pb[p];
        }
        __syncthreads();

        if (kt+1 < KT) load_tile(kt+1);

        #pragma unroll
        for (int g2=0; g2<2; g2++){
            uint32_t av[4][4];
            #pragma unroll
            for (int i=0;i<4;i++){
                int mtc = wm*4 + i;
                uint4 v = *(const uint4*)&sA[st][((g2*8 + mtc)*32 + (lp ^ g2))*4];
                av[i][0]=v.x; av[i][1]=v.y; av[i][2]=v.z; av[i][3]=v.w;
            }
            uint32_t bv[4][2];
            #pragma unroll
            for (int j=0;j<4;j++){
                int ntc = wn*4 + j;
                uint2 v = *(const uint2*)&sB[st][((g2*16 + ntc)*32 + (lp ^ g2 ^ ((ntc&1)<<1)))*2];
                bv[j][0]=v.x; bv[j][1]=v.y;
            }
            #pragma unroll
            for (int i=0;i<4;i++)
                #pragma unroll
                for (int j=0;j<4;j++){
                    asm volatile(
                        "mma.sync.aligned.m16n8k16.row.col.f32.bf16.bf16.f32 "
                        "{%0,%1,%2,%3}, {%4,%5,%6,%7}, {%8,%9}, {%0,%1,%2,%3};"
                        : "+f"(acc[i][j][0]), "+f"(acc[i][j][1]),
                          "+f"(acc[i][j][2]), "+f"(acc[i][j][3])
                        : "r"(av[i][0]), "r"(av[i][1]), "r"(av[i][2]), "r"(av[i][3]),
                          "r"(bv[j][0]), "r"(bv[j][1]));
                }
        }
    }

    int g4c = lane >> 2, tc = lane & 3;
    #pragma unroll
    for (int i=0;i<4;i++){
        int row = m0 + (wm*4 + i)*16 + g4c;
        #pragma unroll
        for (int j=0;j<4;j++){
            int col = n0 + (wn*4 + j)*8 + tc*2;
            float b0 = bias[col], b1 = bias[col+1];
            *(float2*)(C + (size_t)row*ldc + col) =
                make_float2(softplus_(acc[i][j][0]+b0), softplus_(acc[i][j][1]+b1));
            *(float2*)(C + (size_t)(row+8)*ldc + col) =
                make_float2(softplus_(acc[i][j][2]+b0), softplus_(acc[i][j][3]+b1));
        }
    }
}

// ---------------- conv + SiLU, 2 channels/thread (bf16x2); zeroes dbc ----------------
__global__ void conv_silu_kernel(const bf16* __restrict__ xz, const float* __restrict__ cw,
                                 const float* __restrict__ cb, bf16* __restrict__ xc,
                                 float* __restrict__ dbc)
{
    int idx2 = blockIdx.x*blockDim.x + threadIdx.x;   // NTOK*DI/2 total
    if (idx2 < NTOK*XPE/2) *(float2*)(dbc + idx2*2) = make_float2(0.f, 0.f);
    int dh  = idx2 % (DI/2);
    int d   = dh * 2;
    int tok = idx2 / (DI/2);
    int l = tok % LL, b = tok / LL;
    float2 bias = *(const float2*)(cb + d);
    float a0 = bias.x, a1 = bias.y;
    float4 w0 = *(const float4*)(cw + d*4);       // ch d:  w[0..3]
    float4 w1 = *(const float4*)(cw + d*4 + 4);   // ch d+1: w[0..3]
    float wa[4] = {w0.x, w0.y, w0.z, w0.w};
    float wb[4] = {w1.x, w1.y, w1.z, w1.w};
    #pragma unroll
    for (int j=0;j<4;j++){
        int li = l - 3 + j;
        if (li >= 0){
            __nv_bfloat162 v = *(const __nv_bfloat162*)(xz + (size_t)(b*LL+li)*(2*DI) + d);
            a0 = fmaf(wa[j], __bfloat162float(v.x), a0);
            a1 = fmaf(wb[j], __bfloat162float(v.y), a1);
        }
    }
    a0 = a0 * sigmoidf_(a0);
    a1 = a1 * sigmoidf_(a1);
    *(__nv_bfloat162*)(xc + (size_t)tok*DI + d) = __floats2bfloat162_rn(a0, a1);
}

// ---------------- segmented scan pass 1 (R12-proven) ----------------
__global__ void __launch_bounds__(256)
scan_sum_kernel(const float* __restrict__ delta, const bf16* __restrict__ xc,
                const float* __restrict__ dbc, const float* __restrict__ A_log,
                float* __restrict__ sumA, float* __restrict__ sumB)
{
    __shared__ float s_delta[SEGL][16];
    __shared__ float s_x[SEGL][16];
    __shared__ float s_B[SEGL][16];

    int tid  = threadIdx.x;
    int bdb  = blockIdx.x % NGB;
    int seg  = blockIdx.x / NGB;
    int gg   = bdb*16 + (tid>>4);
    int n    = tid & 15;
    int b    = gg / DI;
    int d    = gg % DI;
    int d0   = (bdb*16) % DI;
    int t0   = seg * SEGL;

    int lj = tid & 15, lt0 = tid >> 4;
    #pragma unroll
    for (int k=0;k<4;k++){
        int t = lt0 + k*16;
        int tok = b*LL + t0 + t;
        s_delta[t][lj] = delta[(size_t)tok*DI + d0 + lj];
        s_x[t][lj]     = __bfloat162float(xc[(size_t)tok*DI + d0 + lj]);
        s_B[t][lj]     = dbc[(size_t)tok*XPE + DD + lj];
    }
    float An = -expf(A_log[d*DS + n]);
    __syncthreads();

    int dj = tid >> 4;
    float h = 0.f, Ap = 1.f;
    #pragma unroll 4
    for (int t=0;t<SEGL;t++){
        float dlt = s_delta[t][dj];
        float xv  = s_x[t][dj];
        float Bn  = s_B[t][n];
        float dA  = __expf(dlt*An);
        Ap *= dA;
        h = fmaf(dA, h, dlt*Bn*xv);
    }
    int L = gg*16 + n;
    sumA[seg*LANES + L] = Ap;
    sumB[seg*LANES + L] = h;
}

// ---------------- segmented scan pass 2 (R12-proven) ----------------
__global__ void __launch_bounds__(256)
scan_apply_kernel(const float* __restrict__ delta, const bf16* __restrict__ xc,
                  const float* __restrict__ dbc, const bf16* __restrict__ xz,
                  const float* __restrict__ A_log, const float* __restrict__ Dp,
                  const float* __restrict__ sumA, const float* __restrict__ sumB,
                  fp8* __restrict__ out)
{
    __shared__ float s_delta[SEGL][16];
    __shared__ float s_x[SEGL][16];
    __shared__ float s_z[SEGL][16];
    __shared__ float s_B[SEGL][16];
    __shared__ float s_C[SEGL][16];

    int tid  = threadIdx.x;
    int bdb  = blockIdx.x % NGB;
    int seg  = blockIdx.x / NGB;
    int gg   = bdb*16 + (tid>>4);
    int n    = tid & 15;
    int b    = gg / DI;
    int d    = gg % DI;
    int d0   = (bdb*16) % DI;
    int t0   = seg * SEGL;

    int lj = tid & 15, lt0 = tid >> 4;
    #pragma unroll
    for (int k=0;k<4;k++){
        int t = lt0 + k*16;
        int tok = b*LL + t0 + t;
        s_delta[t][lj] = delta[(size_t)tok*DI + d0 + lj];
        s_x[t][lj]     = __bfloat162float(xc[(size_t)tok*DI + d0 + lj]);
        s_z[t][lj]     = __bfloat162float(xz[(size_t)tok*(2*DI) + DI + d0 + lj]);
        s_B[t][lj]     = dbc[(size_t)tok*XPE + DD + lj];
        s_C[t][lj]     = dbc[(size_t)tok*XPE + DD + DS + lj];
    }

    float An = -expf(A_log[d*DS + n]);
    float Dd = Dp[d];

    int L = gg*16 + n;
    float h = 0.f;
    for (int s=0; s<seg; s++)
        h = fmaf(sumA[s*LANES + L], h, sumB[s*LANES + L]);

    __syncthreads();

    int dj = tid >> 4;
    #pragma unroll 4
    for (int t=0;t<SEGL;t++){
        float dlt = s_delta[t][dj];
        float xv  = s_x[t][dj];
        float dA  = __expf(dlt*An);
        h = fmaf(dA, h, dlt*s_B[t][n]*xv);
        float y = h*s_C[t][n];
        y += __shfl_xor_sync(0xffffffffu, y, 1);
        y += __shfl_xor_sync(0xffffffffu, y, 2);
        y += __shfl_xor_sync(0xffffffffu, y, 4);
        y += __shfl_xor_sync(0xffffffffu, y, 8);
        if (n == 0){
            float z  = s_z[t][dj];
            float sv = y + Dd*xv;
            out[(size_t)(b*LL + t0 + t)*DI + d] =
                f2e4(sv * z * (1.f/(1.f+__expf(-z))));
        }
    }
}

// ---------------- launcher ----------------
extern "C" void kernel_launch(void* const* d_in, const int* in_sizes, int n_in,
                              void* d_out, int out_size)
{
    const float* x       = (const float*)d_in[0];
    const float* in_w    = (const float*)d_in[1];
    const float* conv_w  = (const float*)d_in[2];
    const float* conv_b  = (const float*)d_in[3];
    const float* xproj_w = (const float*)d_in[4];
    const float* dt_w    = (const float*)d_in[5];
    const float* dt_b    = (const float*)d_in[6];
    const float* A_log   = (const float*)d_in[7];
    const float* Dp      = (const float*)d_in[8];
    const float* out_w   = (const float*)d_in[9];
    const float* norm_w  = (const float*)d_in[10];
    float* res = (float*)d_out;

    fp8 *xn, *y, *inw8, *ow8;
    bf16 *xz, *xc, *xpw, *dtw;
    float *dbc, *delta, *sumA, *sumB;
    cudaGetSymbolAddress((void**)&xn,    g8_xn);
    cudaGetSymbolAddress((void**)&xz,    gb_xz);
    cudaGetSymbolAddress((void**)&xc,    gb_xc);
    cudaGetSymbolAddress((void**)&dbc,   g_dbc);
    cudaGetSymbolAddress((void**)&delta, g_delta);
    cudaGetSymbolAddress((void**)&y,     g8_y);
    cudaGetSymbolAddress((void**)&sumA,  g_sumA);
    cudaGetSymbolAddress((void**)&sumB,  g_sumB);
    cudaGetSymbolAddress((void**)&inw8,  g8_inw);
    cudaGetSymbolAddress((void**)&ow8,   g8_ow);
    cudaGetSymbolAddress((void**)&xpw,   gb_xpw);
    cudaGetSymbolAddress((void**)&dtw,   gb_dtw);

    const int GSMEM = 49152;   // 3 stages x (8KB A + 8KB B)
    cudaFuncSetAttribute(gemm_cp<3,1,false>, cudaFuncAttributeMaxDynamicSharedMemorySize, GSMEM);
    cudaFuncSetAttribute(gemm_cp<1,1,false>, cudaFuncAttributeMaxDynamicSharedMemorySize, GSMEM);
    cudaFuncSetAttribute(gemm_cp<1,2,true>,  cudaFuncAttributeMaxDynamicSharedMemorySize, GSMEM);

    // residual stream lives in d_out
    cudaMemcpyAsync(res, x, (size_t)NTOK*DM*sizeof(float), cudaMemcpyDeviceToDevice, 0);

    // weight converts (2 kernels -> in_proj gemm is kernel #4)
    {
        int na = 2*2*DI*DM, nb = 2*DM*DI;
        wq2_kernel<<<((na+nb)/4+255)/256, 256>>>(in_w, inw8, na, out_w, ow8, nb);
    }
    {
        int na = 2*XPE*DI, nb = 2*DI*DD;
        f2bf2_kernel<<<((na+nb)/4+255)/256, 256>>>(xproj_w, xpw, na, dt_w, dtw, nb);
    }

    for (int l=0;l<2;l++){
        rmsnorm_kernel<<<NTOK, 256>>>(res, norm_w + l*DM, xn);

        // xz = (xn @ in_w^T)/64  (fp8 cp.async gemm, bf16 store)  <- kernel #4 on l=0
        gemm_cp<3,1,false><<<dim3(2*DI/128, NTOK/128, 1), 256, GSMEM>>>(
            xn, inw8 + (size_t)l*2*DI*DM, xz,
            NTOK, 2*DI, DM, DM, DM, 2*DI);

        conv_silu_kernel<<<(NTOK*DI/2)/256, 256>>>(xz, conv_w + l*DI*4, conv_b + l*DI,
                                                   xc, dbc);

        // dbc = xc @ xproj_w^T  (bf16 cp.async gemm, split-K=8, atomics; dbc zeroed by conv)
        gemm_cp<1,2,true><<<dim3(1, NTOK/128, 8), 256, GSMEM>>>(
            (const uint8_t*)xc, (const uint8_t*)(xpw + (size_t)l*XPE*DI), dbc,
            NTOK, XPE, (DI/8)*2, DI*2, DI*2, XPE);

        // delta = softplus(dbc[:,:48] @ dt_w^T + dt_b)  (register-staging bf16, K=48)
        gemm_dt<<<dim3(DI/128, NTOK/128, 1), 256>>>(
            dbc, dtw + (size_t)l*DI*DD, dt_b + l*DI, delta,
            NTOK, DI, DD, XPE, DD, DI);

        scan_sum_kernel<<<NGB*NSEG, 256>>>(delta, xc, dbc,
                                           A_log + (size_t)l*DI*DS, sumA, sumB);
        scan_apply_kernel<<<NGB*NSEG, 256>>>(delta, xc, dbc, xz,
                                             A_log + (size_t)l*DI*DS, Dp + l*DI,
                                             sumA, sumB, y);

        // res += (y @ out_w^T)/64  (fp8, split-K=3 => one full wave)
        gemm_cp<1,1,false><<<dim3(DM/128, NTOK/128, 3), 256, GSMEM>>>(
            y, ow8 + (size_t)l*DM*DI, res,
            NTOK, DM, DI/3, DI, DI, DM);
    }
}